// round 8
// baseline (speedup 1.0000x reference)
#include <cuda_runtime.h>
#include <cuda_bf16.h>
#include <cstdint>

#define HID 256
#define MAXN 100000
#define MAXE 400000
#define MAXN_PAD 100096

// ---------------- scratch (device globals; no allocation allowed) ----------------
__device__ float g_h0_node[(size_t)MAXN * HID];
__device__ float g_hnA    [(size_t)MAXN * HID];
__device__ float g_hnB    [(size_t)MAXN * HID];
__device__ float g_h0_edge[(size_t)MAXE * HID];
__device__ float g_edge_a [(size_t)MAXE * HID];
__device__ float g_edge_b [(size_t)MAXE * HID];
__device__ float g_aggF   [(size_t)MAXN * HID];
__device__ float g_h2     [(size_t)MAXN * HID];
__device__ __align__(16) float g_padN[(size_t)MAXN_PAD * 160];
__device__ __align__(16) float g_padE[(size_t)MAXE * 160];

// transposed + bf16-split weights: Wt[n][k], K-major, zero-padded to Kpad
__device__ __align__(16) __nv_bfloat16 g_WtA_hi[(size_t)HID * 160];
__device__ __align__(16) __nv_bfloat16 g_WtA_lo[(size_t)HID * 160];
__device__ __align__(16) __nv_bfloat16 g_WtB_hi[(size_t)HID * 160];
__device__ __align__(16) __nv_bfloat16 g_WtB_lo[(size_t)HID * 160];
__device__ __align__(16) __nv_bfloat16 g_WtH_hi[(size_t)3 * HID * HID];
__device__ __align__(16) __nv_bfloat16 g_WtH_lo[(size_t)3 * HID * HID];
__device__ __align__(16) __nv_bfloat16 g_WtLR_hi[(size_t)HID * 768];
__device__ __align__(16) __nv_bfloat16 g_WtLR_lo[(size_t)HID * 768];
__device__ __align__(16) __nv_bfloat16 g_WtO_hi [(size_t)HID * 512];
__device__ __align__(16) __nv_bfloat16 g_WtO_lo [(size_t)HID * 512];

__device__ __forceinline__ uint32_t smem_u32(const void* p) {
    uint32_t a;
    asm("{ .reg .u64 t; cvta.to.shared.u64 t, %1; cvt.u32.u64 %0, t; }" : "=r"(a) : "l"(p));
    return a;
}

#define LDMX4(r, addr) \
    asm volatile("ldmatrix.sync.aligned.m8n8.x4.shared.b16 {%0,%1,%2,%3}, [%4];" \
        : "=r"((r)[0]), "=r"((r)[1]), "=r"((r)[2]), "=r"((r)[3]) : "r"(addr))

#define LDS128F(v, addr) \
    asm volatile("ld.shared.v4.f32 {%0,%1,%2,%3}, [%4];" \
        : "=f"((v).x), "=f"((v).y), "=f"((v).z), "=f"((v).w) : "r"(addr))

#define STS64U(addr, a0, a1) \
    asm volatile("st.shared.v2.b32 [%0], {%1,%2};" :: "r"(addr), "r"(a0), "r"(a1))

#define MMA(d, a, b0_, b1_) \
    asm volatile("mma.sync.aligned.m16n8k16.row.col.f32.bf16.bf16.f32 " \
        "{%0,%1,%2,%3}, {%4,%5,%6,%7}, {%8,%9}, {%0,%1,%2,%3};" \
        : "+f"((d)[0]), "+f"((d)[1]), "+f"((d)[2]), "+f"((d)[3]) \
        : "r"((a)[0]), "r"((a)[1]), "r"((a)[2]), "r"((a)[3]), "r"(b0_), "r"(b1_))

#define CPA16(dst_u32, src_ptr) \
    asm volatile("cp.async.cg.shared.global [%0], [%1], 16;" \
        :: "r"(dst_u32), "l"(src_ptr) : "memory")
#define CPA_COMMIT() asm volatile("cp.async.commit_group;" ::: "memory")
#define CPA_WAIT0()  asm volatile("cp.async.wait_group 0;" ::: "memory")

// split fp32 pair -> bf16x2 hi + bf16x2 lo (RN, exact residual)
__device__ __forceinline__ void split2(float x, float y, uint32_t& hi, uint32_t& lo) {
    asm("cvt.rn.bf16x2.f32 %0, %1, %2;" : "=r"(hi) : "f"(y), "f"(x));
    float fx = __uint_as_float(hi << 16);
    float fy = __uint_as_float(hi & 0xffff0000u);
    float lx = x - fx, ly = y - fy;
    asm("cvt.rn.bf16x2.f32 %0, %1, %2;" : "=r"(lo) : "f"(ly), "f"(lx));
}

enum { MODE_IN2 = 0, MODE_MSG = 1, MODE_CAT3 = 2, MODE_OUT = 3 };

// --------- bf16x3 tensor-core GEMM, register-staged A, pure ldmatrix+MMA hot loop ---------
// Block tile 128(M) x 128(N), grid.y covers N=256. 8 warps: 4(M) x 2(N).
// smem: convA bf16 hi|lo [2 x 16K] | B bf16 hi|lo [2 x 16K] | (MSG) raw rev fp32 [2 x 16K]
template<int MODE, bool RED_, bool WRITE_>
__global__ __launch_bounds__(256, 2)
void tgemm_k(const float* __restrict__ A,
             const __nv_bfloat16* __restrict__ Whi, const __nv_bfloat16* __restrict__ Wlo,
             float* __restrict__ C, float* __restrict__ C2, float* __restrict__ R,
             const int* __restrict__ ridx,
             const float* __restrict__ P1, const float* __restrict__ P2,
             const float* __restrict__ P3, const int* __restrict__ sidx,
             const float* __restrict__ bias, int M, int Kpad)
{
    extern __shared__ __align__(16) uint8_t smem[];
    const uint32_t sAu  = smem_u32(smem);          // convA: 2 x 16K
    const uint32_t sBu  = sAu + 32768u;            // B:     2 x 16K
    const uint32_t sRu  = sAu + 65536u;            // rev raw (MSG only): 2 x 16K

    const int tid  = threadIdx.x;
    const int lane = tid & 31;
    const int wid  = tid >> 5;
    const int wm   = wid & 3;
    const int wn   = wid >> 2;
    const int row0 = blockIdx.x * 128;
    const int nb   = blockIdx.y * 128;

    float acc[2][8][4];
#pragma unroll
    for (int t = 0; t < 2; t++)
#pragma unroll
        for (int n = 0; n < 8; n++)
#pragma unroll
            for (int q = 0; q < 4; q++) acc[t][n][q] = 0.f;

    const int g  = lane >> 3;
    const int i2 = lane & 7;
    const int nst = Kpad >> 5;

    float4 q[4];   // register-staged A chunks (this thread's 4 x 16B of the A tile)

    // issue async loads for tile st into buffer buf: LDG main A stream -> q,
    // cp.async B (and MSG rev stream) -> smem
    auto ldg_stage = [&](int st, int buf) {
        const int k0 = st << 5;
        // B tile cp.async
        const uint32_t bB = sBu + (uint32_t)buf * 16384u;
#pragma unroll
        for (int it = 0; it < 4; it++) {
            int idx = it * 256 + tid;
            int var = idx >> 9, rem = idx & 511;
            int r = rem >> 2, c = rem & 3;
            const __nv_bfloat16* W = var ? Wlo : Whi;
            const __nv_bfloat16* srcp = W + (size_t)(nb + r) * Kpad + k0 + c * 8;
            CPA16(bB + (uint32_t)r * 128 + ((uint32_t)((var * 4 + c) ^ (r & 7)) << 4), srcp);
        }
        // MSG rev stream cp.async (raw fp32)
        if (MODE == MODE_MSG) {
            const uint32_t rB = sRu + (uint32_t)buf * 16384u;
#pragma unroll
            for (int it = 0; it < 4; it++) {
                int idx = it * 256 + tid;
                int r = idx >> 3, c = idx & 7;
                int grow = row0 + r; if (grow >= M) grow = M - 1;
                const float* srcp = P2 + (size_t)(grow ^ 1) * HID + k0 + c * 4;
                CPA16(rB + (uint32_t)r * 128 + ((uint32_t)(c ^ (r & 7)) << 4), srcp);
            }
        }
        CPA_COMMIT();
        // main A stream LDG (latency hidden under the MMA phase)
#pragma unroll
        for (int it = 0; it < 4; it++) {
            int idx = it * 256 + tid;
            int r = idx >> 3, c = idx & 7;
            int grow = row0 + r; if (grow >= M) grow = M - 1;
            int gk = k0 + c * 4;
            const float* s0;
            if (MODE == MODE_IN2) {
                s0 = A + (size_t)grow * Kpad + gk;
            } else if (MODE == MODE_MSG) {
                int s = __ldg(&sidx[grow]);
                s0 = P1 + (size_t)s * HID + gk;
            } else if (MODE == MODE_CAT3) {
                const float* p = (gk < 256) ? P1 : (gk < 512) ? P2 : P3;
                s0 = p + (size_t)grow * HID + (gk & 255);
            } else {
                const float* p = (gk < 256) ? P1 : P2;
                s0 = p + (size_t)grow * HID + (gk & 255);
            }
            q[it] = *(const float4*)s0;
        }
    };

    // convert staged regs (minus rev stream for MSG) -> bf16 hi|lo A tile in smem
    auto convert = [&](int buf) {
        const uint32_t aB = sAu + (uint32_t)buf * 16384u;
        const uint32_t rB = sRu + (uint32_t)buf * 16384u;
#pragma unroll
        for (int it = 0; it < 4; it++) {
            int idx = it * 256 + tid;
            int r = idx >> 3, c = idx & 7;
            float4 v = q[it];
            if (MODE == MODE_MSG) {
                float4 w;
                LDS128F(w, rB + (uint32_t)r * 128 + ((uint32_t)(c ^ (r & 7)) << 4));
                v.x -= w.x; v.y -= w.y; v.z -= w.z; v.w -= w.w;
            }
            uint32_t h0, l0, h1, l1;
            split2(v.x, v.y, h0, l0);
            split2(v.z, v.w, h1, l1);
            uint32_t base = aB + (uint32_t)r * 128 + ((uint32_t)(c & 1) << 3);
            STS64U(base + ((uint32_t)(((c >> 1)    ) ^ (r & 7)) << 4), h0, h1);
            STS64U(base + ((uint32_t)(((c >> 1) + 4) ^ (r & 7)) << 4), l0, l1);
        }
    };

    // prologue: stage + convert tile 0
    ldg_stage(0, 0);
    CPA_WAIT0();
    convert(0);
    __syncthreads();

    for (int st = 0; st < nst; st++) {
        const int buf = st & 1;
        if (st + 1 < nst) ldg_stage(st + 1, buf ^ 1);   // LDG + cp.async overlap MMAs

        const uint32_t aBase = sAu + (uint32_t)buf * 16384u;
        const uint32_t bBase = sBu + (uint32_t)buf * 16384u;
#pragma unroll
        for (int kc = 0; kc < 2; kc++) {
            // A fragments via ldmatrix (R4-proven addressing)
            uint32_t ah[2][4], al[2][4];
#pragma unroll
            for (int t = 0; t < 2; t++) {
                int rowm = wm * 32 + t * 16 + (g & 1) * 8 + i2;
                uint32_t rb = (uint32_t)rowm * 128;
                LDMX4(ah[t], aBase + rb + ((uint32_t)((2 * kc + (g >> 1)    ) ^ (rowm & 7)) << 4));
                LDMX4(al[t], aBase + rb + ((uint32_t)((2 * kc + (g >> 1) + 4) ^ (rowm & 7)) << 4));
            }
            uint32_t bfr[4][4];
#pragma unroll
            for (int p = 0; p < 4; p++) {
                int rn = wn * 64 + p * 16 + (g >> 1) * 8 + i2;
                LDMX4(bfr[p], bBase + (uint32_t)rn * 128
                              + ((uint32_t)((2 * kc + (g & 1)) ^ (rn & 7)) << 4));
            }
            // pass 1: ah x bh
#pragma unroll
            for (int p = 0; p < 4; p++)
#pragma unroll
                for (int t = 0; t < 2; t++) {
                    MMA(acc[t][2 * p],     ah[t], bfr[p][0], bfr[p][1]);
                    MMA(acc[t][2 * p + 1], ah[t], bfr[p][2], bfr[p][3]);
                }
            // pass 2: al x bh
#pragma unroll
            for (int p = 0; p < 4; p++)
#pragma unroll
                for (int t = 0; t < 2; t++) {
                    MMA(acc[t][2 * p],     al[t], bfr[p][0], bfr[p][1]);
                    MMA(acc[t][2 * p + 1], al[t], bfr[p][2], bfr[p][3]);
                }
            // reload B-lo fragments
#pragma unroll
            for (int p = 0; p < 4; p++) {
                int rn = wn * 64 + p * 16 + (g >> 1) * 8 + i2;
                LDMX4(bfr[p], bBase + (uint32_t)rn * 128
                              + ((uint32_t)((2 * kc + (g & 1) + 4) ^ (rn & 7)) << 4));
            }
            // pass 3: ah x bl
#pragma unroll
            for (int p = 0; p < 4; p++)
#pragma unroll
                for (int t = 0; t < 2; t++) {
                    MMA(acc[t][2 * p],     ah[t], bfr[p][0], bfr[p][1]);
                    MMA(acc[t][2 * p + 1], ah[t], bfr[p][2], bfr[p][3]);
                }
        }
        if (st + 1 < nst) {
            CPA_WAIT0();          // rev/B for t+1 landed (rev read by same thread: no sync needed)
            convert(buf ^ 1);     // writes buf^1 regions only — disjoint from buf being read
        }
        __syncthreads();
    }

    // ---- epilogue: write C and/or scatter-RED into R[ridx[row]] ----
    const int coln0 = nb + wn * 64;
#pragma unroll
    for (int t = 0; t < 2; t++) {
#pragma unroll
        for (int s = 0; s < 2; s++) {
            int row = row0 + wm * 32 + t * 16 + (lane >> 2) + s * 8;
            if (row >= M) continue;
            int drow = 0;
            if (RED_) drow = __ldg(&ridx[row]);
#pragma unroll
            for (int n8 = 0; n8 < 8; n8++) {
                int col = coln0 + n8 * 8 + 2 * (lane & 3);
                float ox = acc[t][n8][2 * s], oy = acc[t][n8][2 * s + 1];
                if (MODE == MODE_MSG) {
                    float2 h = *(const float2*)(P3 + (size_t)row * HID + col);
                    ox += h.x; oy += h.y;
                }
                if (MODE == MODE_OUT) {
                    float2 b = *(const float2*)(bias + col);
                    ox += b.x; oy += b.y;
                }
                if (MODE != MODE_CAT3) { ox = fmaxf(ox, 0.f); oy = fmaxf(oy, 0.f); }
                if (WRITE_) {
                    float2 o = make_float2(ox, oy);
                    *(float2*)(C + (size_t)row * HID + col) = o;
                    if (MODE == MODE_IN2 && C2 != nullptr)
                        *(float2*)(C2 + (size_t)row * HID + col) = o;
                }
                if (RED_) {
                    float* p = R + (size_t)drow * HID + col;
                    asm volatile("red.global.add.v2.f32 [%0], {%1,%2};"
                                 :: "l"(p), "f"(ox), "f"(oy) : "memory");
                }
            }
        }
    }
}

// ------- ALL weight transposes + bf16 splits in ONE launch -------
__global__ void wsplit_all_k(
    const float* __restrict__ Wa, const float* __restrict__ Wb, const float* __restrict__ Wh,
    const float* __restrict__ Wlr, const float* __restrict__ Wo,
    __nv_bfloat16* __restrict__ ahi, __nv_bfloat16* __restrict__ alo,
    __nv_bfloat16* __restrict__ bhi, __nv_bfloat16* __restrict__ blo,
    __nv_bfloat16* __restrict__ hhi, __nv_bfloat16* __restrict__ hlo,
    __nv_bfloat16* __restrict__ lrhi, __nv_bfloat16* __restrict__ lrlo,
    __nv_bfloat16* __restrict__ ohi, __nv_bfloat16* __restrict__ olo)
{
    int idx = blockIdx.x * blockDim.x + threadIdx.x;
    if (idx >= 606208) return;
    const float* W; __nv_bfloat16 *hi, *lo; int K, Kpad, local;
    if (idx < 40960)       { local = idx;          W = Wa;  hi = ahi;  lo = alo;  K = 133; Kpad = 160; }
    else if (idx < 81920)  { local = idx - 40960;  W = Wb;  hi = bhi;  lo = blo;  K = 147; Kpad = 160; }
    else if (idx < 278528) { int l = idx - 81920; int d = l >> 16; local = l & 65535;
                             W = Wh + (size_t)d * 65536; hi = hhi + (size_t)d * 65536;
                             lo = hlo + (size_t)d * 65536; K = 256; Kpad = 256; }
    else if (idx < 475136) { local = idx - 278528; W = Wlr; hi = lrhi; lo = lrlo; K = 768; Kpad = 768; }
    else                   { local = idx - 475136; W = Wo;  hi = ohi;  lo = olo;  K = 512; Kpad = 512; }
    int n = local / Kpad, k = local - n * Kpad;
    float v = (k < K) ? W[(size_t)k * HID + n] : 0.f;
    __nv_bfloat16 h = __float2bfloat16(v);
    hi[local] = h;
    lo[local] = __float2bfloat16(v - __bfloat162float(h));
}

// ------- pad raw inputs to stride-160 fp32 -------
__global__ void pad_k(const float* __restrict__ na, const float* __restrict__ ea,
                      float* __restrict__ pn, float* __restrict__ pe,
                      int n_nodes, int n_edges)
{
    long long i = (long long)blockIdx.x * 256 + threadIdx.x;
    long long tn = (long long)n_nodes * 160;
    if (i < tn) {
        int row = (int)(i / 160), k = (int)(i - (long long)row * 160);
        pn[i] = (k < 133) ? na[(size_t)row * 133 + k] : 0.f;
        return;
    }
    i -= tn;
    long long te = (long long)n_edges * 160;
    if (i < te) {
        int row = (int)(i / 160), k = (int)(i - (long long)row * 160);
        pe[i] = (k < 147) ? ea[(size_t)row * 147 + k] : 0.f;
    }
}

__global__ void zero_k(float4* __restrict__ dst, int n4)
{
    int i = blockIdx.x * blockDim.x + threadIdx.x;
    if (i < n4) dst[i] = make_float4(0.f, 0.f, 0.f, 0.f);
}

__global__ void copy_k(const float4* __restrict__ src, float4* __restrict__ dst, int n4)
{
    int i = blockIdx.x * blockDim.x + threadIdx.x;
    if (i < n4) dst[i] = src[i];
}

extern "C" void kernel_launch(void* const* d_in, const int* in_sizes, int n_in,
                              void* d_out, int out_size)
{
    const float* node_attr = (const float*)d_in[0];
    const float* edge_attr = (const float*)d_in[1];
    const int*   src       = (const int*)d_in[2];
    const int*   dst       = (const int*)d_in[3];
    const float* W_i_atom  = (const float*)d_in[4];
    const float* W_i_bond  = (const float*)d_in[5];
    const float* W_h       = (const float*)d_in[6];
    const float* W_o       = (const float*)d_in[7];
    const float* W_o_b     = (const float*)d_in[8];
    const float* W_lr      = (const float*)d_in[9];
    float* out = (float*)d_out;

    const int n_nodes = in_sizes[0] / 133;
    const int n_edges = in_sizes[2];

    float *h0n, *hnA, *hnB, *h0e, *ea, *eb, *agf, *h2, *pn, *pe;
    __nv_bfloat16 *wahi, *walo, *wbhi, *wblo, *whhi, *whlo, *wlrhi, *wlrlo, *wohi, *wolo;
    cudaGetSymbolAddress((void**)&h0n, g_h0_node);
    cudaGetSymbolAddress((void**)&hnA, g_hnA);
    cudaGetSymbolAddress((void**)&hnB, g_hnB);
    cudaGetSymbolAddress((void**)&h0e, g_h0_edge);
    cudaGetSymbolAddress((void**)&ea,  g_edge_a);
    cudaGetSymbolAddress((void**)&eb,  g_edge_b);
    cudaGetSymbolAddress((void**)&agf, g_aggF);
    cudaGetSymbolAddress((void**)&h2,  g_h2);
    cudaGetSymbolAddress((void**)&pn,  g_padN);
    cudaGetSymbolAddress((void**)&pe,  g_padE);
    cudaGetSymbolAddress((void**)&wahi, g_WtA_hi);   cudaGetSymbolAddress((void**)&walo, g_WtA_lo);
    cudaGetSymbolAddress((void**)&wbhi, g_WtB_hi);   cudaGetSymbolAddress((void**)&wblo, g_WtB_lo);
    cudaGetSymbolAddress((void**)&whhi, g_WtH_hi);   cudaGetSymbolAddress((void**)&whlo, g_WtH_lo);
    cudaGetSymbolAddress((void**)&wlrhi, g_WtLR_hi); cudaGetSymbolAddress((void**)&wlrlo, g_WtLR_lo);
    cudaGetSymbolAddress((void**)&wohi, g_WtO_hi);   cudaGetSymbolAddress((void**)&wolo, g_WtO_lo);

    cudaFuncSetAttribute((const void*)tgemm_k<MODE_IN2,  false, true >, cudaFuncAttributeMaxDynamicSharedMemorySize, 65536);
    cudaFuncSetAttribute((const void*)tgemm_k<MODE_IN2,  true,  true >, cudaFuncAttributeMaxDynamicSharedMemorySize, 65536);
    cudaFuncSetAttribute((const void*)tgemm_k<MODE_MSG,  true,  true >, cudaFuncAttributeMaxDynamicSharedMemorySize, 98304);
    cudaFuncSetAttribute((const void*)tgemm_k<MODE_MSG,  true,  false>, cudaFuncAttributeMaxDynamicSharedMemorySize, 98304);
    cudaFuncSetAttribute((const void*)tgemm_k<MODE_CAT3, false, true >, cudaFuncAttributeMaxDynamicSharedMemorySize, 65536);
    cudaFuncSetAttribute((const void*)tgemm_k<MODE_OUT,  false, true >, cudaFuncAttributeMaxDynamicSharedMemorySize, 65536);

    dim3 blk(256);
    dim3 gn((n_nodes + 127) / 128, 2);
    dim3 ge((n_edges + 127) / 128, 2);
    const int n4n = n_nodes * HID / 4;
    const int cpg = (n4n + 255) / 256;
    const long long padtot = (long long)n_nodes * 160 + (long long)n_edges * 160;

    wsplit_all_k<<<(606208 + 255) / 256, 256>>>(W_i_atom, W_i_bond, W_h, W_lr, W_o,
        wahi, walo, wbhi, wblo, whhi, whlo, wlrhi, wlrlo, wohi, wolo);
    pad_k<<<(int)((padtot + 255) / 256), 256>>>(node_attr, edge_attr, pn, pe, n_nodes, n_edges);

    tgemm_k<MODE_IN2, false, true><<<gn, blk, 65536>>>(pn, wahi, walo,
        h0n, hnA, nullptr, nullptr, nullptr, nullptr, nullptr, nullptr, nullptr, n_nodes, 160);
    tgemm_k<MODE_IN2, true, true><<<ge, blk, 65536>>>(pe, wbhi, wblo,
        h0e, nullptr, hnA, dst, nullptr, nullptr, nullptr, nullptr, nullptr, n_edges, 160);

    copy_k<<<cpg, 256>>>((const float4*)hnA, (float4*)hnB, n4n);
    tgemm_k<MODE_MSG, true, true><<<ge, blk, 98304>>>(nullptr,
        whhi + 0 * (size_t)HID * HID, whlo + 0 * (size_t)HID * HID,
        ea, nullptr, hnB, dst, hnA, h0e, h0e, src, nullptr, n_edges, HID);
    zero_k<<<cpg, 256>>>((float4*)agf, n4n);
    copy_k<<<cpg, 256>>>((const float4*)hnB, (float4*)hnA, n4n);
    tgemm_k<MODE_MSG, true, true><<<ge, blk, 98304>>>(nullptr,
        whhi + 1 * (size_t)HID * HID, whlo + 1 * (size_t)HID * HID,
        eb, nullptr, hnA, dst, hnB, ea, h0e, src, nullptr, n_edges, HID);
    tgemm_k<MODE_MSG, true, false><<<ge, blk, 98304>>>(nullptr,
        whhi + 2 * (size_t)HID * HID, whlo + 2 * (size_t)HID * HID,
        nullptr, nullptr, agf, dst, hnA, eb, h0e, src, nullptr, n_edges, HID);

    tgemm_k<MODE_CAT3, false, true><<<gn, blk, 65536>>>(nullptr, wlrhi, wlrlo,
        h2, nullptr, nullptr, nullptr, agf, hnA, h0n, nullptr, nullptr, n_nodes, 768);
    tgemm_k<MODE_OUT, false, true><<<gn, blk, 65536>>>(nullptr, wohi, wolo,
        out, nullptr, nullptr, nullptr, h2, h0n, nullptr, nullptr, W_o_b, n_nodes, 512);
}